// round 7
// baseline (speedup 1.0000x reference)
#include <cuda_runtime.h>

#define NN 8192
#define NE 16384
#define W  256
#define NS (NE / W)          // 64 strips
#define NP 148
#define NC 148
#define TPB 512
#define SLOTS 8
#define RMAXP 7              // producer: ceil(56 rows / 8 row-eighths)
#define KMAXC 8              // consumer: 7 teams * 8 rows

// ---- scratch (device globals; no allocation allowed) ----
__device__ float g_u[NN];
__device__ float g_v[NN];
__device__ float g_c[NN];
__device__ float g_ai[NE];
__device__ float g_ao[NE];
__device__ float g_part[SLOTS][NP][2 * W];
__device__ int   g_doneA[NS];     // producers finished strip s
__device__ int   g_fin[NS];       // ai/ao[s] fully published
__device__ int   g_round[NS + 2]; // consumer rounds completed

__device__ __forceinline__ int ld_acq(const int* p) {
    int v;
    asm volatile("ld.acquire.gpu.s32 %0, [%1];" : "=r"(v) : "l"(p) : "memory");
    return v;
}
__device__ __forceinline__ void f4add(float4& a, const float4 b) {
    a.x += b.x; a.y += b.y; a.z += b.z; a.w += b.w;
}
__device__ __forceinline__ void f4fma(float4& a, const float4 b, float s) {
    a.x += b.x * s; a.y += b.y * s; a.z += b.z * s; a.w += b.w * s;
}
__device__ __forceinline__ float4 ldcs4(const float* p) {   // evict-first (last touch)
    float4 r;
    asm volatile("ld.global.cs.v4.f32 {%0,%1,%2,%3}, [%4];"
                 : "=f"(r.x), "=f"(r.y), "=f"(r.z), "=f"(r.w) : "l"(p));
    return r;
}
__device__ __forceinline__ void bfly4(float4& a, int off) {
    a.x += __shfl_xor_sync(0xffffffffu, a.x, off);
    a.y += __shfl_xor_sync(0xffffffffu, a.y, off);
    a.z += __shfl_xor_sync(0xffffffffu, a.z, off);
    a.w += __shfl_xor_sync(0xffffffffu, a.w, off);
}

__global__ void k1_prep(const float* __restrict__ X, const float* __restrict__ kw) {
    int n = blockIdx.x * blockDim.x + threadIdx.x;
    if (n < NS) { g_doneA[n] = 0; g_fin[n] = 0; }
    if (n < NS + 2) g_round[n] = 0;
    if (n >= NN) return;
    float4 x = reinterpret_cast<const float4*>(X)[n];
    g_u[n] = x.x * kw[0] + x.y * kw[1] + x.z * kw[2]  + x.w * kw[3];
    g_v[n] = x.x * kw[4] + x.y * kw[5] + x.z * kw[6]  + x.w * kw[7];
    g_c[n] = x.x * kw[8] + x.y * kw[9] + x.z * kw[10] + x.w * kw[11];
}

__global__ __launch_bounds__(TPB, 2) void fused(const float* __restrict__ Ri,
                                                const float* __restrict__ Ro,
                                                const float* __restrict__ ew,
                                                float* __restrict__ out) {
    __shared__ float spu[56], spv[56];
    __shared__ float sred[7][2];

    const int t   = threadIdx.x;
    const int cta = blockIdx.x;

    if (cta < NP) {
        // ============ PRODUCER: barrier-free DRAM stream, shuffle-only reduce ============
        const int p  = cta;
        const int r0 = (int)(((long long)p * NN) / NP);
        const int r1 = (int)(((long long)(p + 1) * NN) / NP);
        const int nrows = r1 - r0;
        const int colg = t >> 3;        // 0..63  (float4 col group within strip)
        const int sub  = t & 7;         // 0..7   (row eighth) — adjacent lanes!
        if (t < nrows) { spu[t] = g_u[r0 + t]; spv[t] = g_v[r0 + t]; }
        __syncthreads();

        for (int s = 0; s < NS; ++s) {
            if (s >= 3) {               // lagged gate: footprint + slot reuse
                if (t == 0) { while (ld_acq(&g_round[s - 3]) < NC) __nanosleep(32); }
                __syncthreads();
            }
            float4 pai = make_float4(0.f, 0.f, 0.f, 0.f);
            float4 pao = make_float4(0.f, 0.f, 0.f, 0.f);
            const size_t base = (size_t)(r0 + sub) * NE + (size_t)s * W + colg * 4;
#pragma unroll
            for (int k = 0; k < RMAXP; ++k) {
                const int rr = sub + k * 8;
                if (rr < nrows) {
                    const float4 a = *reinterpret_cast<const float4*>(Ri + base + (size_t)k * 8 * NE);
                    const float4 b = *reinterpret_cast<const float4*>(Ro + base + (size_t)k * 8 * NE);
                    f4fma(pai, b, spu[rr]);    // ai += Ro * u
                    f4fma(pao, a, spv[rr]);    // ao += Ri * v
                }
            }
            // reduce over the 8 adjacent lanes (row-eighths): 3-level butterfly
            bfly4(pai, 1); bfly4(pai, 2); bfly4(pai, 4);
            bfly4(pao, 1); bfly4(pao, 2); bfly4(pao, 4);
            if (sub == 0) {
                const int slot = s & (SLOTS - 1);
                *reinterpret_cast<float4*>(&g_part[slot][p][colg * 4])     = pai;
                *reinterpret_cast<float4*>(&g_part[slot][p][W + colg * 4]) = pao;
                __threadfence();
            }
            __syncthreads();
            if (t == 0) atomicAdd(&g_doneA[s], 1);
        }
    } else {
        // ============ CONSUMER: lagged stages, 1 barrier/round ============
        const int c  = cta - NP;
        const int r0 = (int)(((long long)c * NN) / NC);
        const int r1 = (int)(((long long)(c + 1) * NN) / NC);
        const int nrows = r1 - r0;
        const int team = (t >> 6) - 1;  // 0..6 (dot threads t>=64)
        const int lane = t & 63;        // float4 col group
        const int l32  = t & 31;

        float acc[KMAXC];
#pragma unroll
        for (int k = 0; k < KMAXC; ++k) acc[k] = 0.f;

        // finish-reduce chunk: 128 float4 chunks over 148 CTAs (0 or 1 each)
        const int c_lo = (c * 128) / NC;
        const int c_hi = ((c + 1) * 128) / NC;

        for (int r = 0; r < NS + 2; ++r) {
            // ---- warp0: finish-reduce strip q = r-1 (1 strip behind producers) ----
            const int q = r - 1;
            if (t < 32 && q >= 0 && q < NS) {
                if (t == 0) { while (ld_acq(&g_doneA[q]) < NP) __nanosleep(32); }
                __syncwarp();
                if (c_lo < c_hi) {
                    const int v = c_lo, slot = q & (SLOTS - 1);
                    float4 sum = make_float4(0.f, 0.f, 0.f, 0.f);
                    for (int pp = l32; pp < NP; pp += 32)
                        f4add(sum, *reinterpret_cast<const float4*>(&g_part[slot][pp][v * 4]));
                    bfly4(sum, 16); bfly4(sum, 8); bfly4(sum, 4); bfly4(sum, 2); bfly4(sum, 1);
                    if (l32 == 0) {
                        const int which = v >> 6, cg = v & 63;
                        const float4 wv = *reinterpret_cast<const float4*>(ew + (size_t)q * W + cg * 4);
                        sum.x *= wv.x; sum.y *= wv.y; sum.z *= wv.z; sum.w *= wv.w;
                        float* dst = (which == 0) ? &g_ai[q * W + cg * 4] : &g_ao[q * W + cg * 4];
                        *reinterpret_cast<float4*>(dst) = sum;
                        __threadfence();
                    }
                }
                __syncwarp();
                if (t == 0) atomicAdd(&g_fin[q], 1);
            }
            // ---- dot warps: strip d = r-2 (2 rounds of slack behind fin) ----
            const int d = r - 2;
            if (t >= 64 && d >= 0) {
                if (l32 == 0) { while (ld_acq(&g_fin[d]) < NC) __nanosleep(32); }
                __syncwarp();
                const float4 vai = *reinterpret_cast<const float4*>(&g_ai[d * W + lane * 4]);
                const float4 vao = *reinterpret_cast<const float4*>(&g_ao[d * W + lane * 4]);
                const size_t colA = (size_t)d * W + lane * 4;
#pragma unroll
                for (int k = 0; k < KMAXC; ++k) {
                    const int rr = team + k * 7;
                    if (rr < nrows) {
                        const float4 a = ldcs4(Ri + (size_t)(r0 + rr) * NE + colA);
                        const float4 b = ldcs4(Ro + (size_t)(r0 + rr) * NE + colA);
                        acc[k] += a.x * vai.x + a.y * vai.y + a.z * vai.z + a.w * vai.w
                                + b.x * vao.x + b.y * vao.y + b.z * vao.z + b.w * vao.w;
                    }
                }
            }
            __syncthreads();
            if (t == 0) atomicAdd(&g_round[r], 1);
        }

        // final per-row reduction: 64 lanes (2 warps) per team -> scalar
#pragma unroll
        for (int k = 0; k < KMAXC; ++k) {
            float vsum = (t >= 64) ? acc[k] : 0.f;
#pragma unroll
            for (int off = 16; off; off >>= 1)
                vsum += __shfl_down_sync(0xffffffffu, vsum, off);
            if (t >= 64 && l32 == 0) sred[team][(t >> 5) & 1] = vsum;
            __syncthreads();
            if (t >= 64) {
                const int rr = team + k * 7;
                if (lane == 0 && rr < nrows)
                    out[r0 + rr] = sred[team][0] + sred[team][1] + g_c[r0 + rr];
            }
            __syncthreads();
        }
    }
}

extern "C" void kernel_launch(void* const* d_in, const int* in_sizes, int n_in,
                              void* d_out, int out_size) {
    const float* X    = (const float*)d_in[0];  // [N,4]
    const float* ew   = (const float*)d_in[1];  // [E,1]
    const float* Ri   = (const float*)d_in[2];  // [N,E]
    const float* Ro   = (const float*)d_in[3];  // [N,E]
    const float* kern = (const float*)d_in[4];  // [12,1]
    float* out = (float*)d_out;                 // [N,1]

    k1_prep<<<NN / 256, 256>>>(X, kern);
    fused<<<NP + NC, TPB>>>(Ri, Ro, ew, out);
}

// round 8
// speedup vs baseline: 1.2775x; 1.2775x over previous
#include <cuda_runtime.h>

#define NN 8192
#define NE 16384
#define W  256
#define NS (NE / W)          // 64 strips
#define NP 148
#define NC 148
#define TPB 512
#define SLOTS 8
#define RMAXP 7              // producer: ceil(56 rows / 8 subs)
#define KMAXC 8              // consumer: 7 teams * 8 rows
#define NCHUNK 128           // float4 chunks of ai|ao per strip

// ---- scratch (device globals; no allocation allowed) ----
__device__ float g_u[NN];
__device__ float g_v[NN];
__device__ float g_c[NN];
__device__ float g_ai[NE];
__device__ float g_ao[NE];
__device__ float g_part[SLOTS][NP][2 * W];
__device__ int   g_pdone[NS][NP];     // producer p finished strip s
__device__ int   g_cflag[NS][NCHUNK]; // ai/ao chunk v of strip s published
__device__ int   g_cdone[NS][NC];     // consumer c finished dotting strip s

__device__ __forceinline__ int ld_acq(const int* p) {
    int v;
    asm volatile("ld.acquire.gpu.s32 %0, [%1];" : "=r"(v) : "l"(p) : "memory");
    return v;
}
__device__ __forceinline__ void st_rel(int* p, int v) {
    asm volatile("st.release.gpu.s32 [%0], %1;" :: "l"(p), "r"(v) : "memory");
}
__device__ __forceinline__ void f4add(float4& a, const float4 b) {
    a.x += b.x; a.y += b.y; a.z += b.z; a.w += b.w;
}
__device__ __forceinline__ void f4fma(float4& a, const float4 b, float s) {
    a.x += b.x * s; a.y += b.y * s; a.z += b.z * s; a.w += b.w * s;
}
__device__ __forceinline__ float4 ldcs4(const float* p) {   // evict-first (last touch)
    float4 r;
    asm volatile("ld.global.cs.v4.f32 {%0,%1,%2,%3}, [%4];"
                 : "=f"(r.x), "=f"(r.y), "=f"(r.z), "=f"(r.w) : "l"(p));
    return r;
}
__device__ __forceinline__ void bfly4(float4& a, int off) {
    a.x += __shfl_xor_sync(0xffffffffu, a.x, off);
    a.y += __shfl_xor_sync(0xffffffffu, a.y, off);
    a.z += __shfl_xor_sync(0xffffffffu, a.z, off);
    a.w += __shfl_xor_sync(0xffffffffu, a.w, off);
}
// warp-cooperative wait until flags[0..n) are all nonzero
__device__ __forceinline__ void wait_flags(const int* flags, int n, int l32) {
    for (;;) {
        bool ok = true;
        for (int i = l32; i < n; i += 32) ok &= (ld_acq(&flags[i]) != 0);
        if (__all_sync(0xffffffffu, ok)) return;
        __nanosleep(64);
    }
}

__global__ void k1_prep(const float* __restrict__ X, const float* __restrict__ kw) {
    int n = blockIdx.x * blockDim.x + threadIdx.x;
    // zero all flag arrays (grid-stride)
    int* pd = &g_pdone[0][0];
    for (int i = n; i < NS * NP; i += NN) pd[i] = 0;
    int* cf = &g_cflag[0][0];
    for (int i = n; i < NS * NCHUNK; i += NN) cf[i] = 0;
    int* cd = &g_cdone[0][0];
    for (int i = n; i < NS * NC; i += NN) cd[i] = 0;
    if (n >= NN) return;
    float4 x = reinterpret_cast<const float4*>(X)[n];
    g_u[n] = x.x * kw[0] + x.y * kw[1] + x.z * kw[2]  + x.w * kw[3];
    g_v[n] = x.x * kw[4] + x.y * kw[5] + x.z * kw[6]  + x.w * kw[7];
    g_c[n] = x.x * kw[8] + x.y * kw[9] + x.z * kw[10] + x.w * kw[11];
}

__global__ __launch_bounds__(TPB, 2) void fused(const float* __restrict__ Ri,
                                                const float* __restrict__ Ro,
                                                const float* __restrict__ ew,
                                                float* __restrict__ out) {
    __shared__ float4 sA[TPB];     // 8 KB
    __shared__ float4 sB[TPB];     // 8 KB
    __shared__ float  spu[56], spv[56];
    __shared__ float  sred[7][2];

    const int t   = threadIdx.x;
    const int cta = blockIdx.x;
    const int l32 = t & 31;

    if (cta < NP) {
        // ============ PRODUCER: coalesced barrier-light DRAM stream ============
        const int p  = cta;
        const int r0 = (int)(((long long)p * NN) / NP);
        const int r1 = (int)(((long long)(p + 1) * NN) / NP);
        const int nrows = r1 - r0;
        const int lane = t & 63;        // float4 col group (coalesced!)
        const int sub  = t >> 6;        // 0..7 row eighth
        if (t < nrows) { spu[t] = g_u[r0 + t]; spv[t] = g_v[r0 + t]; }
        __syncthreads();

        for (int s = 0; s < NS; ++s) {
            if (s >= 3) {               // footprint gate, 3 strips of slack
                if (t < 32) wait_flags(g_cdone[s - 3], NC, l32);
                __syncthreads();
            }
            float4 pai = make_float4(0.f, 0.f, 0.f, 0.f);
            float4 pao = make_float4(0.f, 0.f, 0.f, 0.f);
            const size_t colA = (size_t)s * W + lane * 4;
#pragma unroll
            for (int k = 0; k < RMAXP; ++k) {
                const int rr = sub + k * 8;
                if (rr < nrows) {
                    const float4 a = *reinterpret_cast<const float4*>(Ri + (size_t)(r0 + rr) * NE + colA);
                    const float4 b = *reinterpret_cast<const float4*>(Ro + (size_t)(r0 + rr) * NE + colA);
                    f4fma(pai, b, spu[rr]);    // ai += Ro * u
                    f4fma(pao, a, spv[rr]);    // ao += Ri * v
                }
            }
            sA[t] = pai; sB[t] = pao;
            __syncthreads();
            if (t < 256) { f4add(sA[t], sA[t + 256]); f4add(sB[t], sB[t + 256]); }
            __syncthreads();
            if (t < 128) { f4add(sA[t], sA[t + 128]); f4add(sB[t], sB[t + 128]); }
            __syncthreads();
            if (t < 64) {
                float4 rai = sA[t]; f4add(rai, sA[t + 64]);
                float4 rao = sB[t]; f4add(rao, sB[t + 64]);
                const int slot = s & (SLOTS - 1);
                *reinterpret_cast<float4*>(&g_part[slot][p][t * 4])     = rai;
                *reinterpret_cast<float4*>(&g_part[slot][p][W + t * 4]) = rao;
                __threadfence();
            }
            __syncthreads();
            if (t == 0) st_rel(&g_pdone[s][p], 1);   // one store, no serialization
        }
    } else {
        // ============ CONSUMER: lagged stages, flag-based sync ============
        const int c  = cta - NP;
        const int r0 = (int)(((long long)c * NN) / NC);
        const int r1 = (int)(((long long)(c + 1) * NN) / NC);
        const int nrows = r1 - r0;
        const int team = (t >> 6) - 1;  // 0..6 for dot threads t>=64
        const int lane = t & 63;

        float acc[KMAXC];
#pragma unroll
        for (int k = 0; k < KMAXC; ++k) acc[k] = 0.f;

        // finish-reduce chunk: NCHUNK chunks over NC CTAs (0 or 1 each)
        const int c_lo = (c * NCHUNK) / NC;
        const int c_hi = ((c + 1) * NCHUNK) / NC;

        for (int r = 0; r < NS + 2; ++r) {
            // ---- warp0: finish-reduce strip q = r-1 (1 strip behind producers) ----
            const int q = r - 1;
            if (t < 32 && q >= 0 && q < NS) {
                wait_flags(g_pdone[q], NP, l32);
                if (c_lo < c_hi) {
                    const int v = c_lo, slot = q & (SLOTS - 1);
                    float4 sum = make_float4(0.f, 0.f, 0.f, 0.f);
#pragma unroll
                    for (int pp = l32; pp < NP; pp += 32)
                        f4add(sum, *reinterpret_cast<const float4*>(&g_part[slot][pp][v * 4]));
                    bfly4(sum, 16); bfly4(sum, 8); bfly4(sum, 4); bfly4(sum, 2); bfly4(sum, 1);
                    if (l32 == 0) {
                        const int which = v >> 6, cg = v & 63;
                        const float4 wv = *reinterpret_cast<const float4*>(ew + (size_t)q * W + cg * 4);
                        sum.x *= wv.x; sum.y *= wv.y; sum.z *= wv.z; sum.w *= wv.w;
                        float* dst = (which == 0) ? &g_ai[q * W + cg * 4] : &g_ao[q * W + cg * 4];
                        *reinterpret_cast<float4*>(dst) = sum;
                        st_rel(&g_cflag[q][v], 1);    // release orders the value store
                    }
                }
            }
            // ---- dot warps: strip d = r-2 (2 rounds of slack) ----
            const int d = r - 2;
            if (t >= 64 && d >= 0) {
                wait_flags(g_cflag[d], NCHUNK, l32);
                const float4 vai = *reinterpret_cast<const float4*>(&g_ai[d * W + lane * 4]);
                const float4 vao = *reinterpret_cast<const float4*>(&g_ao[d * W + lane * 4]);
                const size_t colA = (size_t)d * W + lane * 4;
#pragma unroll
                for (int k = 0; k < KMAXC; ++k) {
                    const int rr = team + k * 7;
                    if (rr < nrows) {
                        const float4 a = ldcs4(Ri + (size_t)(r0 + rr) * NE + colA);
                        const float4 b = ldcs4(Ro + (size_t)(r0 + rr) * NE + colA);
                        acc[k] += a.x * vai.x + a.y * vai.y + a.z * vai.z + a.w * vai.w
                                + b.x * vao.x + b.y * vao.y + b.z * vao.z + b.w * vao.w;
                    }
                }
            }
            __syncthreads();
            if (t == 0 && d >= 0) st_rel(&g_cdone[d][c], 1);
        }

        // final per-row reduction: 64 lanes (2 warps) per team -> scalar
#pragma unroll
        for (int k = 0; k < KMAXC; ++k) {
            float vsum = (t >= 64) ? acc[k] : 0.f;
#pragma unroll
            for (int off = 16; off; off >>= 1)
                vsum += __shfl_down_sync(0xffffffffu, vsum, off);
            if (t >= 64 && l32 == 0) sred[team][(t >> 5) & 1] = vsum;
            __syncthreads();
            if (t >= 64) {
                const int rr = team + k * 7;
                if (lane == 0 && rr < nrows)
                    out[r0 + rr] = sred[team][0] + sred[team][1] + g_c[r0 + rr];
            }
            __syncthreads();
        }
    }
}

extern "C" void kernel_launch(void* const* d_in, const int* in_sizes, int n_in,
                              void* d_out, int out_size) {
    const float* X    = (const float*)d_in[0];  // [N,4]
    const float* ew   = (const float*)d_in[1];  // [E,1]
    const float* Ri   = (const float*)d_in[2];  // [N,E]
    const float* Ro   = (const float*)d_in[3];  // [N,E]
    const float* kern = (const float*)d_in[4];  // [12,1]
    float* out = (float*)d_out;                 // [N,1]

    k1_prep<<<NN / 256, 256>>>(X, kern);
    fused<<<NP + NC, TPB>>>(Ri, Ro, ew, out);
}

// round 9
// speedup vs baseline: 1.6053x; 1.2566x over previous
#include <cuda_runtime.h>

#define NN 8192
#define NE 16384
#define NCTA 128          // each CTA owns 128 columns (32 quads)
#define TPB 1024
#define QPC 32            // quads per CTA
#define NCH 8             // chunks per CTA, 4 quads (16 cols) each
#define NIT 32            // row iterations: 8192 rows / 256 groups

// smem layout (floats): su[8192] | sv[8192] | sout[8192] | sredA[128 f4] | sredB[128 f4] | seai[4 f4] | seao[4 f4]
#define SMEM_FLOATS (3 * NN + 4 * 128 + 4 * 128 + 16 + 16)
#define SMEM_BYTES (SMEM_FLOATS * 4)

// ---- scratch (device globals; no allocation allowed) ----
__device__ float g_u[NN];
__device__ float g_v[NN];
__device__ float g_c[NN];
__device__ float g_outp[NCTA][NN];

__device__ __forceinline__ void f4add(float4& a, const float4 b) {
    a.x += b.x; a.y += b.y; a.z += b.z; a.w += b.w;
}
__device__ __forceinline__ void f4fma(float4& a, const float4 b, float s) {
    a.x += b.x * s; a.y += b.y * s; a.z += b.z * s; a.w += b.w * s;
}
__device__ __forceinline__ float4 ldcg4(const float* p) {   // L2-resident stream (pass 1)
    float4 r;
    asm volatile("ld.global.cg.v4.f32 {%0,%1,%2,%3}, [%4];"
                 : "=f"(r.x), "=f"(r.y), "=f"(r.z), "=f"(r.w) : "l"(p));
    return r;
}
__device__ __forceinline__ float4 ldcs4(const float* p) {   // evict-first (pass 2, last touch)
    float4 r;
    asm volatile("ld.global.cs.v4.f32 {%0,%1,%2,%3}, [%4];"
                 : "=f"(r.x), "=f"(r.y), "=f"(r.z), "=f"(r.w) : "l"(p));
    return r;
}
__device__ __forceinline__ void bfly4(float4& a, int off) {
    a.x += __shfl_xor_sync(0xffffffffu, a.x, off);
    a.y += __shfl_xor_sync(0xffffffffu, a.y, off);
    a.z += __shfl_xor_sync(0xffffffffu, a.z, off);
    a.w += __shfl_xor_sync(0xffffffffu, a.w, off);
}

// K1: per-node scalars u = X·k1, v = X·k2, c = X·k3
__global__ void k1_prep(const float* __restrict__ X, const float* __restrict__ kw) {
    int n = blockIdx.x * blockDim.x + threadIdx.x;
    if (n >= NN) return;
    float4 x = reinterpret_cast<const float4*>(X)[n];
    g_u[n] = x.x * kw[0] + x.y * kw[1] + x.z * kw[2]  + x.w * kw[3];
    g_v[n] = x.x * kw[4] + x.y * kw[5] + x.z * kw[6]  + x.w * kw[7];
    g_c[n] = x.x * kw[8] + x.y * kw[9] + x.z * kw[10] + x.w * kw[11];
}

// Main kernel: column-partitioned, CTA-local two-pass with software pipelining.
// Phase s: pass1 streams chunk s (16 cols) from DRAM computing pi/pv;
//          pass2 re-reads chunk s-1 from L2 dotting against eai/eao.
__global__ __launch_bounds__(TPB, 1) void big(const float* __restrict__ Ri,
                                              const float* __restrict__ Ro,
                                              const float* __restrict__ ew) {
    extern __shared__ float smem[];
    float*  su    = smem;
    float*  sv    = smem + NN;
    float*  sout  = smem + 2 * NN;
    float4* sredA = reinterpret_cast<float4*>(smem + 3 * NN);       // [32 warps][4 quads]
    float4* sredB = sredA + 128;
    float4* seai  = sredB + 128;                                    // [4]
    float4* seao  = seai + 4;                                       // [4]

    const int t   = threadIdx.x;
    const int cta = blockIdx.x;
    const int g   = t >> 2;          // row group 0..255
    const int ql  = t & 3;           // quad lane within 16-col chunk
    const int w   = t >> 5;          // warp id

    for (int i = t; i < NN; i += TPB) { su[i] = g_u[i]; sv[i] = g_v[i]; sout[i] = 0.f; }
    __syncthreads();

    const int qbase = cta * QPC;

    for (int s = 0; s <= NCH; ++s) {
        const bool P1 = (s < NCH);
        const bool P2 = (s >= 1);
        const size_t colA = (size_t)(qbase + s * 4 + ql) * 4;
        const size_t colB = colA - 16;     // previous chunk, same quad lane
        float4 pai = make_float4(0.f, 0.f, 0.f, 0.f);
        float4 pao = make_float4(0.f, 0.f, 0.f, 0.f);
        float4 eaiB = make_float4(0.f, 0.f, 0.f, 0.f);
        float4 eaoB = make_float4(0.f, 0.f, 0.f, 0.f);
        if (P2) { eaiB = seai[ql]; eaoB = seao[ql]; }  // published at end of prev phase

#pragma unroll 4
        for (int i = 0; i < NIT; ++i) {
            const int n = i * 256 + g;
            const size_t rowoff = (size_t)n * NE;
            if (P1) {   // DRAM leg: col-reduce partials for chunk s
                const float4 a = ldcg4(Ri + rowoff + colA);
                const float4 b = ldcg4(Ro + rowoff + colA);
                const float un = su[n], vn = sv[n];
                f4fma(pai, b, un);     // pi  += Ro * u   (-> ai)
                f4fma(pao, a, vn);     // pv  += Ri * v   (-> ao)
            }
            if (P2) {   // L2 leg: row-dot chunk s-1
                const float4 a = ldcs4(Ri + rowoff + colB);
                const float4 b = ldcs4(Ro + rowoff + colB);
                float dot = a.x * eaiB.x + a.y * eaiB.y + a.z * eaiB.z + a.w * eaiB.w
                          + b.x * eaoB.x + b.y * eaoB.y + b.z * eaoB.z + b.w * eaoB.w;
                dot += __shfl_xor_sync(0xffffffffu, dot, 1);
                dot += __shfl_xor_sync(0xffffffffu, dot, 2);
                if (ql == 0) sout[n] += dot;
            }
        }

        if (P1) {
            // reduce pai/pao over the warp's 8 row-groups (lanes ql, ql+4, ..., ql+28)
            bfly4(pai, 4); bfly4(pai, 8); bfly4(pai, 16);
            bfly4(pao, 4); bfly4(pao, 8); bfly4(pao, 16);
            if ((t & 31) < 4) { sredA[w * 4 + ql] = pai; sredB[w * 4 + ql] = pao; }
        }
        __syncthreads();
        if (P1 && t < 64) {
            // cross-warp reduce (32 warps) + scale by e, publish eai/eao for chunk s
            const bool isB = (t >= 32);
            const int  tt  = t & 31;
            const int  qll = tt & 3;
            const int  seg = tt >> 2;          // 8 segments x 4 warps
            const float4* src = isB ? sredB : sredA;
            float4 sum = make_float4(0.f, 0.f, 0.f, 0.f);
#pragma unroll
            for (int j = 0; j < 4; ++j) f4add(sum, src[(seg * 4 + j) * 4 + qll]);
            bfly4(sum, 4); bfly4(sum, 8); bfly4(sum, 16);
            if (tt < 4) {
                const float4 wv = *reinterpret_cast<const float4*>(ew + (qbase + s * 4 + qll) * 4);
                sum.x *= wv.x; sum.y *= wv.y; sum.z *= wv.z; sum.w *= wv.w;
                if (isB) seao[qll] = sum; else seai[qll] = sum;
            }
        }
        __syncthreads();
    }

    for (int i = t; i < NN; i += TPB) g_outp[cta][i] = sout[i];
}

// Final: out[n] = sum_p outp[p][n] + c[n]   (deterministic fixed order)
__global__ void kfin(float* __restrict__ out) {
    const int n = blockIdx.x * blockDim.x + threadIdx.x;
    if (n >= NN) return;
    float s = g_c[n];
#pragma unroll 8
    for (int p = 0; p < NCTA; ++p) s += g_outp[p][n];
    out[n] = s;
}

extern "C" void kernel_launch(void* const* d_in, const int* in_sizes, int n_in,
                              void* d_out, int out_size) {
    const float* X    = (const float*)d_in[0];  // [N,4]
    const float* ew   = (const float*)d_in[1];  // [E,1]
    const float* Ri   = (const float*)d_in[2];  // [N,E]
    const float* Ro   = (const float*)d_in[3];  // [N,E]
    const float* kern = (const float*)d_in[4];  // [12,1]
    float* out = (float*)d_out;                 // [N,1]

    cudaFuncSetAttribute(big, cudaFuncAttributeMaxDynamicSharedMemorySize, SMEM_BYTES);
    k1_prep<<<NN / 256, 256>>>(X, kern);
    big<<<NCTA, TPB, SMEM_BYTES>>>(Ri, Ro, ew);
    kfin<<<NN / 256, 256>>>(out);
}